// round 2
// baseline (speedup 1.0000x reference)
#include <cuda_runtime.h>
#include <cuda_bf16.h>

// loss[s] = -(1/496)*[ sum_i x_i*(31-i) - sum_{i<j} ln(e_i+e_j) + 0.0005*sum_i x_i^2*(31-2i) ]
// via log_sigmoid(x_i - x_j) == x_i - ln(e^{x_i} + e^{x_j}).
//
// Two segments per warp, packed as f32x2. Pair enumeration by ring offsets
// o=1..15 (each unordered pair once) + o=16 (each twice, weight 0.5), read
// from a duplicated shared-memory ring with immediate offsets (no index ALU).

static constexpr float INV_PAIRS = 1.0f / 496.0f;
static constexpr float LN2  = 0.69314718055994530942f;
static constexpr float L2E  = 1.44269504088896340736f;
static constexpr int   WPB  = 8;   // warps per block

typedef unsigned long long u64;

__device__ __forceinline__ u64 pk(float lo, float hi) {
    u64 r; asm("mov.b64 %0,{%1,%2};" : "=l"(r) : "f"(lo), "f"(hi)); return r;
}
__device__ __forceinline__ void upk(u64 v, float& lo, float& hi) {
    asm("mov.b64 {%0,%1},%2;" : "=f"(lo), "=f"(hi) : "l"(v));
}
__device__ __forceinline__ u64 add2(u64 a, u64 b) {
    u64 r; asm("add.rn.f32x2 %0,%1,%2;" : "=l"(r) : "l"(a), "l"(b)); return r;
}
__device__ __forceinline__ u64 mul2(u64 a, u64 b) {
    u64 r; asm("mul.rn.f32x2 %0,%1,%2;" : "=l"(r) : "l"(a), "l"(b)); return r;
}
__device__ __forceinline__ u64 fma2(u64 a, u64 b, u64 c) {
    u64 r; asm("fma.rn.f32x2 %0,%1,%2,%3;" : "=l"(r) : "l"(a), "l"(b), "l"(c)); return r;
}
__device__ __forceinline__ float ex2(float x) {
    float r; asm("ex2.approx.f32 %0,%1;" : "=f"(r) : "f"(x)); return r;
}
__device__ __forceinline__ float lg2(float x) {
    float r; asm("lg2.approx.f32 %0,%1;" : "=f"(r) : "f"(x)); return r;
}

__global__ __launch_bounds__(WPB * 32)
void rmloss_kernel(const float* __restrict__ logits,
                   float2* __restrict__ out,
                   int n_seg)
{
    __shared__ u64 sh[WPB][64];

    const int w    = threadIdx.x >> 5;
    const int lane = threadIdx.x & 31;
    const int gw   = blockIdx.x * WPB + w;          // warp index
    const int s0   = gw * 2;                        // first of two segments
    if (s0 >= n_seg) return;

    // Coalesced loads: two adjacent 128B segments.
    const float xA = logits[s0 * 32 + lane];
    const float xB = logits[s0 * 32 + 32 + lane];
    const u64  x2v = pk(xA, xB);

    // e = exp(x) = exp2(x * log2e): one packed mul + two MUFU.EX2
    u64 xl = mul2(x2v, pk(L2E, L2E));
    float fA, fB; upk(xl, fA, fB);
    const u64 e2 = pk(ex2(fA), ex2(fB));

    // Duplicated ring in shared memory -> pair reads are LDS [base + imm].
    sh[w][lane]      = e2;
    sh[w][lane + 32] = e2;
    __syncwarp();

    // Pair term: sum over offsets of log2(e_l + e_{l+o}), accumulated in base-2.
    u64 acc0 = 0ull, acc1 = 0ull;   // two packed accumulators (break dep chain)
    #pragma unroll
    for (int o = 1; o <= 15; ++o) {
        u64 s = add2(e2, sh[w][lane + o]);
        float sA, sB; upk(s, sA, sB);
        u64 l = pk(lg2(sA), lg2(sB));
        if (o & 1) acc0 = add2(acc0, l); else acc1 = add2(acc1, l);
    }
    {   // offset 16: each remaining pair hit twice -> weight 0.5
        u64 s = add2(e2, sh[w][lane + 16]);
        float sA, sB; upk(s, sA, sB);
        u64 l = pk(lg2(sA), lg2(sB));
        acc1 = fma2(l, pk(0.5f, 0.5f), acc1);
    }
    u64 acc = add2(acc0, acc1);

    // Closed-form terms: x*(31-lane) + 0.0005*x^2*(31-2*lane), packed.
    const float cl = (float)(31 - lane);
    const float cq = 0.0005f * (float)(31 - 2 * lane);
    u64 v = mul2(x2v, pk(cl, cl));
    v = fma2(mul2(x2v, x2v), pk(cq, cq), v);

    // v -= ln2 * acc  (pair log sum was in base 2)
    v = fma2(acc, pk(-LN2, -LN2), v);

    // Butterfly reduction over 64-bit packed value (2 SHFL + 1 packed add / step).
    #pragma unroll
    for (int m = 16; m >= 1; m >>= 1) {
        u64 o = __shfl_xor_sync(0xFFFFFFFFu, v, m);
        v = add2(v, o);
    }

    if (lane == 0) {
        float vA, vB; upk(v, vA, vB);
        out[gw] = make_float2(-vA * INV_PAIRS, -vB * INV_PAIRS);
    }
}

extern "C" void kernel_launch(void* const* d_in, const int* in_sizes, int n_in,
                              void* d_out, int out_size)
{
    const float* logits = (const float*)d_in[0];
    float2* out = (float2*)d_out;
    const int n_seg = out_size;                 // 32768

    const int threads = WPB * 32;               // 8 warps -> 16 segments/block
    const int segs_per_block = WPB * 2;
    const int blocks = (n_seg + segs_per_block - 1) / segs_per_block;
    rmloss_kernel<<<blocks, threads>>>(logits, out, n_seg);
}

// round 3
// speedup vs baseline: 1.2362x; 1.2362x over previous
#include <cuda_runtime.h>
#include <cuda_bf16.h>

// loss[s] = -(1/496)*[ sum_i x_i*(31-i) - sum_{i<j} ln(e_i+e_j) + 0.0005*sum_i x_i^2*(31-2i) ]
// via log_sigmoid(x_i - x_j) == x_i - ln(e^{x_i} + e^{x_j}).
//
// Key trick: sum_{pairs} ln(t) = ln(prod t). Each lane multiplies its 16 pair
// terms into a running product with integer-exponent renormalization, then
// takes ONE lg2 at the end. MUFU per warp: 4 (was 34).

static constexpr float INV_PAIRS = 1.0f / 496.0f;
static constexpr float LN2  = 0.69314718055994530942f;
static constexpr float L2E  = 1.44269504088896340736f;
static constexpr int   WPB  = 8;   // warps per block

typedef unsigned long long u64;
typedef unsigned int u32;

__device__ __forceinline__ u64 pk(float lo, float hi) {
    u64 r; asm("mov.b64 %0,{%1,%2};" : "=l"(r) : "f"(lo), "f"(hi)); return r;
}
__device__ __forceinline__ void upk(u64 v, float& lo, float& hi) {
    asm("mov.b64 {%0,%1},%2;" : "=f"(lo), "=f"(hi) : "l"(v));
}
__device__ __forceinline__ u64 add2(u64 a, u64 b) {
    u64 r; asm("add.rn.f32x2 %0,%1,%2;" : "=l"(r) : "l"(a), "l"(b)); return r;
}
__device__ __forceinline__ u64 mul2(u64 a, u64 b) {
    u64 r; asm("mul.rn.f32x2 %0,%1,%2;" : "=l"(r) : "l"(a), "l"(b)); return r;
}
__device__ __forceinline__ u64 fma2(u64 a, u64 b, u64 c) {
    u64 r; asm("fma.rn.f32x2 %0,%1,%2,%3;" : "=l"(r) : "l"(a), "l"(b), "l"(c)); return r;
}
__device__ __forceinline__ float ex2(float x) {
    float r; asm("ex2.approx.f32 %0,%1;" : "=f"(r) : "f"(x)); return r;
}
__device__ __forceinline__ float lg2(float x) {
    float r; asm("lg2.approx.f32 %0,%1;" : "=f"(r) : "f"(x)); return r;
}

// Renormalize packed product: pull raw exponents into int accumulators,
// reset both mantissas into [1,2). Exact (bit manipulation only).
__device__ __forceinline__ void renorm(u64& p, int& eA, int& eB) {
    float a, b; upk(p, a, b);
    u32 ba = __float_as_uint(a), bb = __float_as_uint(b);
    eA += (int)(ba >> 23);
    eB += (int)(bb >> 23);
    a = __uint_as_float((ba & 0x007FFFFFu) | 0x3F800000u);
    b = __uint_as_float((bb & 0x007FFFFFu) | 0x3F800000u);
    p = pk(a, b);
}

__global__ __launch_bounds__(WPB * 32)
void rmloss_kernel(const float* __restrict__ logits,
                   float2* __restrict__ out,
                   int n_seg)
{
    __shared__ u64 sh[WPB][64];

    const int w    = threadIdx.x >> 5;
    const int lane = threadIdx.x & 31;
    const int gw   = blockIdx.x * WPB + w;          // warp index
    const int s0   = gw * 2;                        // first of two segments
    if (s0 >= n_seg) return;

    // Coalesced loads: two adjacent 128B segments per warp.
    const float xA = logits[s0 * 32 + lane];
    const float xB = logits[s0 * 32 + 32 + lane];
    const u64  x2v = pk(xA, xB);

    // e = exp(x) = exp2(x * log2e)
    u64 xl = mul2(x2v, pk(L2E, L2E));
    float fA, fB; upk(xl, fA, fB);
    const u64 e2 = pk(ex2(fA), ex2(fB));

    // Duplicated ring in shared -> pair reads are LDS.64 [base + imm].
    sh[w][lane]      = e2;
    sh[w][lane + 32] = e2;
    __syncwarp();

    // Product of pair terms (e_l + e_{l+o}), o = 1..16.
    // Offsets 1..15: each unordered pair exactly once.
    // Offset 16: only lanes 0..15 contribute (each remaining pair once).
    u64 p = pk(1.0f, 1.0f);
    int eA = 0, eB = 0;
    #pragma unroll
    for (int o = 1; o <= 16; ++o) {
        u64 t = add2(e2, sh[w][lane + o]);
        if (o == 16 && lane >= 16) t = pk(1.0f, 1.0f);
        p = mul2(p, t);
        if (o == 8) renorm(p, eA, eB);
    }
    renorm(p, eA, eB);   // mantissas now in [1,2); true log2(prod) = (e-254) + lg2(m)

    // One lg2 per segment-half.
    float mA, mB; upk(p, mA, mB);
    const float slgA = (float)(eA - 254) + lg2(mA);
    const float slgB = (float)(eB - 254) + lg2(mB);

    // Closed-form terms: x*(31-lane) + 0.0005*x^2*(31-2*lane), packed.
    const float cl = (float)(31 - lane);
    const float cq = 0.0005f * (float)(31 - 2 * lane);
    u64 v = mul2(x2v, pk(cl, cl));
    v = fma2(mul2(x2v, x2v), pk(cq, cq), v);

    // v -= ln2 * log2(prod)   (pair log-sum in base 2)
    v = fma2(pk(slgA, slgB), pk(-LN2, -LN2), v);

    // Butterfly reduction over packed 64-bit value.
    #pragma unroll
    for (int m = 16; m >= 1; m >>= 1) {
        u64 o = __shfl_xor_sync(0xFFFFFFFFu, v, m);
        v = add2(v, o);
    }

    if (lane == 0) {
        float vA, vB; upk(v, vA, vB);
        out[gw] = make_float2(-vA * INV_PAIRS, -vB * INV_PAIRS);
    }
}

extern "C" void kernel_launch(void* const* d_in, const int* in_sizes, int n_in,
                              void* d_out, int out_size)
{
    const float* logits = (const float*)d_in[0];
    float2* out = (float2*)d_out;
    const int n_seg = out_size;                 // 32768

    const int threads = WPB * 32;               // 8 warps -> 16 segments/block
    const int segs_per_block = WPB * 2;
    const int blocks = (n_seg + segs_per_block - 1) / segs_per_block;
    rmloss_kernel<<<blocks, threads>>>(logits, out, n_seg);
}